// round 8
// baseline (speedup 1.0000x reference)
#include <cuda_runtime.h>
#include <math.h>

// Problem constants
#define B_   256
#define S_   200
#define NQ_  400
#define K_   4
#define M_   50
#define KD_  50
#define VD_  200
#define FD_  50
#define NQT  (NQ_ + 1)        // 401 q values
#define NROW (NQT * K_)       // 1604 (q,r) rows
#define CHUNK 8
#define NCHUNK (S_ / CHUNK)   // 25
#define EA_ROWS 16
#define EA_BLOCKS ((NROW + EA_ROWS - 1) / EA_ROWS)   // 101

// ---------------- Precomputed tables (device scratch) ----------------
__device__ float g_corr_tab[NQT * M_];       // softmax(tanh(qemb@Wqk)@key^T)
__device__ float g_sumq_tab[NQT * FD_];      // qemb @ W_sum[200:250] + b_sum
__device__ float g_beta_tab[NQT * 4];        // tanh(qemb@W_th + b_th) (padded)
__device__ float g_dq_tab[NQT];              // qemb @ W_disc[50:100] + b_disc
__device__ float g_ea_tab[NROW * VD_ * 2];   // interleaved (erase, add) per (q,r) row

// ---------------- Kernel 1: fused q-tables + erase/add tables --------
__global__ void prep_kernel(const float* __restrict__ q_tab,
                            const float* __restrict__ key_mem,
                            const float* __restrict__ W_qk,
                            const float* __restrict__ b_qk,
                            const float* __restrict__ W_sum,
                            const float* __restrict__ b_sum,
                            const float* __restrict__ W_th,
                            const float* __restrict__ b_th,
                            const float* __restrict__ W_disc,
                            const float* __restrict__ b_disc,
                            const float* __restrict__ W_v3,
                            const float* __restrict__ b_v,
                            const float* __restrict__ W_e,
                            const float* __restrict__ b_e,
                            const float* __restrict__ W_a,
                            const float* __restrict__ b_a)
{
    int t = threadIdx.x;

    if (blockIdx.x < NQT) {
        // ================= qtab part =================
        int q = blockIdx.x;
        __shared__ float qe[KD_];
        __shared__ float qk[KD_];
        __shared__ float lg[M_];
        __shared__ float red[2];

        if (t < KD_) qe[t] = q_tab[q * KD_ + t];
        __syncthreads();

        if (t < KD_) {
            float acc = b_qk[t];
            #pragma unroll 10
            for (int d = 0; d < KD_; d++) acc = fmaf(qe[d], W_qk[d * KD_ + t], acc);
            qk[t] = tanhf(acc);
            float s = b_sum[t];
            #pragma unroll 10
            for (int d = 0; d < KD_; d++) s = fmaf(qe[d], W_sum[(VD_ + d) * FD_ + t], s);
            g_sumq_tab[q * FD_ + t] = s;
        }
        if (t >= 64 && t < 67) {
            int j = t - 64;
            float acc = b_th[j];
            for (int d = 0; d < KD_; d++) acc = fmaf(qe[d], W_th[d * 3 + j], acc);
            g_beta_tab[q * 4 + j] = tanhf(acc);
        }
        if (t == 96) {
            float acc = b_disc[0];
            for (int d = 0; d < KD_; d++) acc = fmaf(qe[d], W_disc[KD_ + d], acc);
            g_dq_tab[q] = acc;
        }
        __syncthreads();

        if (t < M_) {
            float acc = 0.f;
            #pragma unroll 10
            for (int d = 0; d < KD_; d++) acc = fmaf(qk[d], key_mem[t * KD_ + d], acc);
            lg[t] = acc;
        }
        __syncthreads();
        if (t == 0) {
            float mx = -1e30f;
            for (int m = 0; m < M_; m++) mx = fmaxf(mx, lg[m]);
            red[0] = mx;
        }
        __syncthreads();
        if (t < M_) lg[t] = expf(lg[t] - red[0]);
        __syncthreads();
        if (t == 0) {
            float s = 0.f;
            for (int m = 0; m < M_; m++) s += lg[m];
            red[1] = 1.f / s;
        }
        __syncthreads();
        if (t < M_) g_corr_tab[q * M_ + t] = lg[t] * red[1];
    } else {
        // ================= erase/add part =================
        __shared__ float ve[EA_ROWS][VD_];
        int row0 = (blockIdx.x - NQT) * EA_ROWS;

        for (int i = t; i < EA_ROWS * VD_; i += blockDim.x) {
            int rr = i / VD_;
            int d  = i - rr * VD_;
            int row = row0 + rr;
            if (row < NROW) {
                int q = row >> 2;
                int r = row & 3;
                float val = b_v[d];
                if (q > 0) {
                    int idx = q - 1;
                    #pragma unroll
                    for (int k = 0; k < K_; k++) {
                        int dd = (k > r) ? (k - r) : (r - k);
                        float wc = 1.0f - (float)dd / 3.0f;
                        if (wc > 0.0f)
                            val = fmaf(wc, W_v3[(k * NQ_ + idx) * VD_ + d], val);
                    }
                }
                ve[rr][d] = val;
            }
        }
        __syncthreads();

        if (t < VD_) {
            int v = t;
            float acce[EA_ROWS], acca[EA_ROWS];
            #pragma unroll
            for (int rr = 0; rr < EA_ROWS; rr++) { acce[rr] = 0.f; acca[rr] = 0.f; }
            for (int d = 0; d < VD_; d++) {
                float we = W_e[d * VD_ + v];
                float wa = W_a[d * VD_ + v];
                #pragma unroll
                for (int rr = 0; rr < EA_ROWS; rr++) {
                    float x = ve[rr][d];
                    acce[rr] = fmaf(x, we, acce[rr]);
                    acca[rr] = fmaf(x, wa, acca[rr]);
                }
            }
            float bev = b_e[v], bav = b_a[v];
            #pragma unroll
            for (int rr = 0; rr < EA_ROWS; rr++) {
                int row = row0 + rr;
                if (row < NROW) {
                    float2 ea;
                    ea.x = 1.0f / (1.0f + expf(-(acce[rr] + bev)));   // erase
                    ea.y = tanhf(acca[rr] + bav);                     // add
                    *reinterpret_cast<float2*>(&g_ea_tab[(row * VD_ + v) * 2]) = ea;
                }
            }
        }
    }
}

// ---------------- Kernel 2: phase-pipelined chunked scan -------------
__device__ __forceinline__ float softplusf(float x) {
    return (x > 20.0f) ? x : log1pf(expf(x));
}

__global__ __launch_bounds__(256, 2)
void scan_kernel(const int* __restrict__ q_data,
                 const int* __restrict__ r_data,
                 const float* __restrict__ init_mem,
                 const float* __restrict__ W_sum,
                 const float* __restrict__ W_ab,
                 const float* __restrict__ b_ab,
                 const float* __restrict__ W_disc,
                 float* __restrict__ out)
{
    int b = blockIdx.x;
    int t = threadIdx.x;
    int v = t;                 // column ownership for t < 200
    int f = t % FD_;
    int quarter = t / FD_;
    int l = t & 31;            // lane
    int wj = t >> 5;           // warp id == step-within-chunk for epilogue

    __shared__ float2 ea_sm[CHUNK][VD_];        // 12.8 KB staged (erase,add)
    __shared__ float  w_sm[CHUNK][52];          // staged correlation weights
    __shared__ float  rbuf[2][CHUNK][VD_];      // double-buffered read vectors
    __shared__ float  part_buf[CHUNK][VD_];     // summary partials (chunk c-1)
    __shared__ int    q_row[S_];
    __shared__ int    r_row[S_];

    const int base = b * S_;
    for (int i = t; i < S_; i += 256) {
        q_row[i] = q_data[base + i];
        r_row[i] = r_data[base + i];
    }

    float mv[M_];          // scalar memory state
    float Wreg[FD_];       // scalar W_sum column
    if (t < VD_) {
        #pragma unroll
        for (int m = 0; m < M_; m++) mv[m] = init_mem[m * VD_ + v];
        #pragma unroll
        for (int i = 0; i < FD_; i++)
            Wreg[i] = W_sum[(quarter * FD_ + i) * FD_ + f];
    }

    // per-lane epilogue constants (same for every warp)
    float wab1 = W_ab[l];
    float wd1  = W_disc[l];
    float wab2 = (l + 32 < FD_) ? W_ab[l + 32]   : 0.f;
    float wd2  = (l + 32 < FD_) ? W_disc[l + 32] : 0.f;
    float b_ab0 = b_ab[0];
    __syncthreads();   // q_row/r_row ready

    // Pipeline over c = 0..NCHUNK:
    //   phase1(c):  stage tables for chunk c; prefetch epilogue operands (c-1)
    //   BAR A
    //   phase2(c):  update chunk c -> rbuf[c&1]  ||  summary c-1 from rbuf[(c-1)&1]
    //   BAR B
    //   phase3(c):  epilogue chunk c-1 (8 warps, one step each)
    for (int c = 0; c <= NCHUNK; c++) {
        const int s0 = c * CHUNK;          // staging chunk start
        const int p0 = s0 - CHUNK;         // processing (epilogue/summary) chunk start

        // ---- phase 1: stage chunk c tables ----
        if (c < NCHUNK) {
            if (t < VD_) {
                for (int j = 0; j < CHUNK; j++) {
                    int qq = q_row[s0 + j], rr = r_row[s0 + j];
                    ea_sm[j][t] = __ldg(reinterpret_cast<const float2*>(
                                      &g_ea_tab[((qq * 4 + rr) * VD_ + t) * 2]));
                }
            }
            for (int i = t; i < CHUNK * M_; i += 256) {
                int j = i / M_, m = i - j * M_;
                w_sm[j][m] = __ldg(&g_corr_tab[q_row[s0 + j] * M_ + m]);
            }
        }

        // ---- epilogue operand prefetch for chunk c-1 (warp wj owns step p0+wj)
        float sq1 = 0.f, sq2 = 0.f, be0 = 0.f, be1 = 0.f, be2 = 0.f, dq = 0.f;
        if (c >= 1) {
            int qe_ = q_row[p0 + wj];
            sq1 = __ldg(&g_sumq_tab[qe_ * FD_ + l]);
            if (l + 32 < FD_) sq2 = __ldg(&g_sumq_tab[qe_ * FD_ + l + 32]);
            if (l == 0) {
                be0 = g_beta_tab[qe_ * 4 + 0];
                be1 = g_beta_tab[qe_ * 4 + 1];
                be2 = g_beta_tab[qe_ * 4 + 2];
                dq  = g_dq_tab[qe_];
            }
        }
        __syncthreads();                               // BAR A

        // ---- phase 2: update(c) || summary(c-1), both in t<200 ----
        if (t < VD_) {
            if (c < NCHUNK) {
                float* rb = &rbuf[c & 1][0][0];
                for (int j = 0; j < CHUNK; j++) {
                    float2 ea = ea_sm[j][v];
                    float e = ea.x, a = ea.y;
                    float rd0 = 0.f, rd1 = 0.f;
                    #pragma unroll
                    for (int m = 0; m < M_; m += 2) {
                        float2 w2 = *reinterpret_cast<const float2*>(&w_sm[j][m]);
                        float o0 = mv[m], o1 = mv[m + 1];
                        rd0 = fmaf(w2.x, o0, rd0);
                        rd1 = fmaf(w2.y, o1, rd1);
                        mv[m]     = fmaf(w2.x, fmaf(-o0, e, a), o0);
                        mv[m + 1] = fmaf(w2.y, fmaf(-o1, e, a), o1);
                    }
                    rb[j * VD_ + v] = rd0 + rd1;
                }
            }
            if (c >= 1) {
                const float* rbp = &rbuf[(c - 1) & 1][0][0];
                const int qb = quarter * FD_;
                for (int j = 0; j < CHUNK; j++) {
                    const float* rp = &rbp[j * VD_ + qb];
                    float a0 = 0.f, a1 = 0.f;
                    #pragma unroll
                    for (int i = 0; i < FD_; i += 2) {
                        float2 r2 = *reinterpret_cast<const float2*>(&rp[i]);
                        a0 = fmaf(r2.x, Wreg[i],     a0);
                        a1 = fmaf(r2.y, Wreg[i + 1], a1);
                    }
                    part_buf[j][t] = a0 + a1;
                }
            }
        }
        __syncthreads();                               // BAR B

        // ---- phase 3: epilogue for chunk c-1 (8 warps concurrent) ----
        if (c >= 1) {
            float th_p, al_p;
            {
                float Sf = part_buf[wj][l] + part_buf[wj][l + 50] +
                           part_buf[wj][l + 100] + part_buf[wj][l + 150] + sq1;
                float sf = tanhf(Sf);
                th_p = sf * wab1;
                al_p = sf * wd1;
            }
            if (l + 32 < FD_) {
                int f2 = l + 32;
                float Sf = part_buf[wj][f2] + part_buf[wj][f2 + 50] +
                           part_buf[wj][f2 + 100] + part_buf[wj][f2 + 150] + sq2;
                float sf = tanhf(Sf);
                th_p = fmaf(sf, wab2, th_p);
                al_p = fmaf(sf, wd2, al_p);
            }
            #pragma unroll
            for (int o = 16; o > 0; o >>= 1) {
                th_p += __shfl_down_sync(0xffffffffu, th_p, o);
                al_p += __shfl_down_sync(0xffffffffu, al_p, o);
            }
            if (l == 0) {
                float theta = 3.0f * (th_p + b_ab0);
                float alpha = softplusf(al_p + dq);
                float d0 = theta - be0;
                float d1 = theta - be1;
                float d2 = theta - be2;
                float c0 = alpha * d0;
                float c1 = alpha * (d0 + d1);
                float c2 = alpha * (d0 + d1 + d2);
                float mx = fmaxf(0.0f, fmaxf(c0, fmaxf(c1, c2)));
                float e0 = expf(0.0f - mx);
                float e1 = expf(c0 - mx);
                float e2 = expf(c1 - mx);
                float e3 = expf(c2 - mx);
                float inv = 1.0f / (e0 + e1 + e2 + e3);
                float4 p = make_float4(e0 * inv, e1 * inv, e2 * inv, e3 * inv);
                reinterpret_cast<float4*>(out)[base + p0 + wj] = p;
            }
        }
        // Hazard audit:
        //  ea_sm/w_sm:  write p1(c) -> read p2(c) sep by BAR A(c); readers(c)
        //               finish before BAR B(c) < writes p1(c+1).
        //  rbuf[c&1]:   write p2(c) -> read p2(c+1) sep by BAR B(c)+BAR A(c+1);
        //               rewrite p2(c+2) after BAR A(c+2) > readers p2(c+1).
        //  part_buf:    write p2(c) -> read p3(c) sep by BAR B(c); rewrite
        //               p2(c+1) after BAR A(c+1) > all p3(c) readers.
        //  epi-prefetch regs are per-thread; q_row is read-only after init.
    }
}

// ---------------- launch ---------------------------------------------
extern "C" void kernel_launch(void* const* d_in, const int* in_sizes, int n_in,
                              void* d_out, int out_size)
{
    const int*   q_data   = (const int*)  d_in[0];
    const int*   r_data   = (const int*)  d_in[1];
    const float* q_tab    = (const float*)d_in[2];
    const float* key_mem  = (const float*)d_in[3];
    const float* init_mem = (const float*)d_in[4];
    const float* W_qk     = (const float*)d_in[5];
    const float* b_qk     = (const float*)d_in[6];
    const float* W_v3     = (const float*)d_in[7];
    const float* b_v      = (const float*)d_in[8];
    const float* W_e      = (const float*)d_in[9];
    const float* b_e      = (const float*)d_in[10];
    const float* W_a      = (const float*)d_in[11];
    const float* b_a      = (const float*)d_in[12];
    const float* W_sum    = (const float*)d_in[13];
    const float* b_sum    = (const float*)d_in[14];
    const float* W_ab     = (const float*)d_in[15];
    const float* b_ab     = (const float*)d_in[16];
    const float* W_th     = (const float*)d_in[17];
    const float* b_th     = (const float*)d_in[18];
    const float* W_disc   = (const float*)d_in[19];
    const float* b_disc   = (const float*)d_in[20];
    float* out = (float*)d_out;

    prep_kernel<<<NQT + EA_BLOCKS, 256>>>(q_tab, key_mem, W_qk, b_qk,
                                          W_sum, b_sum, W_th, b_th,
                                          W_disc, b_disc,
                                          W_v3, b_v, W_e, b_e, W_a, b_a);
    scan_kernel<<<B_, 256>>>(q_data, r_data, init_mem, W_sum, W_ab, b_ab,
                             W_disc, out);
}

// round 9
// speedup vs baseline: 1.1488x; 1.1488x over previous
#include <cuda_runtime.h>
#include <math.h>

// Problem constants
#define B_   256
#define S_   200
#define NQ_  400
#define K_   4
#define M_   50
#define KD_  50
#define VD_  200
#define FD_  50
#define NQT  (NQ_ + 1)        // 401 q values
#define NROW (NQT * K_)       // 1604 (q,r) rows
#define CHUNK 8
#define NCHUNK (S_ / CHUNK)   // 25

// ---------------- Precomputed tables (device scratch) ----------------
__device__ float g_corr_tab[NQT * M_];       // softmax(tanh(qemb@Wqk)@key^T)
__device__ float g_sumq_tab[NQT * FD_];      // qemb @ W_sum[200:250] + b_sum
__device__ float g_beta_tab[NQT * 4];        // tanh(qemb@W_th + b_th) (padded)
__device__ float g_dq_tab[NQT];              // qemb @ W_disc[50:100] + b_disc
__device__ float g_ea_tab[NROW * VD_ * 2];   // interleaved (erase, add) per (q,r) row

// ---------------- Kernel 1: q-indexed tables -------------------------
__global__ void qtab_kernel(const float* __restrict__ q_tab,
                            const float* __restrict__ key_mem,
                            const float* __restrict__ W_qk,
                            const float* __restrict__ b_qk,
                            const float* __restrict__ W_sum,
                            const float* __restrict__ b_sum,
                            const float* __restrict__ W_th,
                            const float* __restrict__ b_th,
                            const float* __restrict__ W_disc,
                            const float* __restrict__ b_disc)
{
    int q = blockIdx.x;
    int t = threadIdx.x;
    __shared__ float qe[KD_];
    __shared__ float qk[KD_];
    __shared__ float lg[M_];
    __shared__ float red[2];

    if (t < KD_) qe[t] = q_tab[q * KD_ + t];
    __syncthreads();

    if (t < KD_) {
        float acc = b_qk[t];
        #pragma unroll 10
        for (int d = 0; d < KD_; d++) acc = fmaf(qe[d], W_qk[d * KD_ + t], acc);
        qk[t] = tanhf(acc);
        float s = b_sum[t];
        #pragma unroll 10
        for (int d = 0; d < KD_; d++) s = fmaf(qe[d], W_sum[(VD_ + d) * FD_ + t], s);
        g_sumq_tab[q * FD_ + t] = s;
    }
    if (t < 3) {
        float acc = b_th[t];
        for (int d = 0; d < KD_; d++) acc = fmaf(qe[d], W_th[d * 3 + t], acc);
        g_beta_tab[q * 4 + t] = tanhf(acc);
    }
    if (t == 63) {
        float acc = b_disc[0];
        for (int d = 0; d < KD_; d++) acc = fmaf(qe[d], W_disc[KD_ + d], acc);
        g_dq_tab[q] = acc;
    }
    __syncthreads();

    if (t < M_) {
        float acc = 0.f;
        #pragma unroll 10
        for (int d = 0; d < KD_; d++) acc = fmaf(qk[d], key_mem[t * KD_ + d], acc);
        lg[t] = acc;
    }
    __syncthreads();
    if (t == 0) {
        float mx = -1e30f;
        for (int m = 0; m < M_; m++) mx = fmaxf(mx, lg[m]);
        red[0] = mx;
    }
    __syncthreads();
    if (t < M_) lg[t] = expf(lg[t] - red[0]);
    __syncthreads();
    if (t == 0) {
        float s = 0.f;
        for (int m = 0; m < M_; m++) s += lg[m];
        red[1] = 1.f / s;
    }
    __syncthreads();
    if (t < M_) g_corr_tab[q * M_ + t] = lg[t] * red[1];
}

// ---------------- Kernel 2: erase/add tables over 1604 rows ----------
#define EA_ROWS 16
__global__ void ea_kernel(const float* __restrict__ W_v3,
                          const float* __restrict__ b_v,
                          const float* __restrict__ W_e,
                          const float* __restrict__ b_e,
                          const float* __restrict__ W_a,
                          const float* __restrict__ b_a)
{
    __shared__ float ve[EA_ROWS][VD_];
    int t = threadIdx.x;
    int row0 = blockIdx.x * EA_ROWS;

    for (int i = t; i < EA_ROWS * VD_; i += blockDim.x) {
        int rr = i / VD_;
        int d  = i - rr * VD_;
        int row = row0 + rr;
        if (row < NROW) {
            int q = row >> 2;
            int r = row & 3;
            float val = b_v[d];
            if (q > 0) {
                int idx = q - 1;
                #pragma unroll
                for (int k = 0; k < K_; k++) {
                    int dd = (k > r) ? (k - r) : (r - k);
                    float wc = 1.0f - (float)dd / 3.0f;
                    if (wc > 0.0f)
                        val = fmaf(wc, W_v3[(k * NQ_ + idx) * VD_ + d], val);
                }
            }
            ve[rr][d] = val;
        }
    }
    __syncthreads();

    if (t < VD_) {
        int v = t;
        float acce[EA_ROWS], acca[EA_ROWS];
        #pragma unroll
        for (int rr = 0; rr < EA_ROWS; rr++) { acce[rr] = 0.f; acca[rr] = 0.f; }
        for (int d = 0; d < VD_; d++) {
            float we = W_e[d * VD_ + v];
            float wa = W_a[d * VD_ + v];
            #pragma unroll
            for (int rr = 0; rr < EA_ROWS; rr++) {
                float x = ve[rr][d];
                acce[rr] = fmaf(x, we, acce[rr]);
                acca[rr] = fmaf(x, wa, acca[rr]);
            }
        }
        float bev = b_e[v], bav = b_a[v];
        #pragma unroll
        for (int rr = 0; rr < EA_ROWS; rr++) {
            int row = row0 + rr;
            if (row < NROW) {
                float2 ea;
                ea.x = 1.0f / (1.0f + expf(-(acce[rr] + bev)));   // erase
                ea.y = tanhf(acca[rr] + bav);                     // add
                *reinterpret_cast<float2*>(&g_ea_tab[(row * VD_ + v) * 2]) = ea;
            }
        }
    }
}

// ---------------- Kernel 3: chunked scan, 4-way ILP reductions -------
__device__ __forceinline__ float softplusf(float x) {
    return (x > 20.0f) ? x : log1pf(expf(x));
}

__global__ __launch_bounds__(256, 2)
void scan_kernel(const int* __restrict__ q_data,
                 const int* __restrict__ r_data,
                 const float* __restrict__ init_mem,
                 const float* __restrict__ W_sum,
                 const float* __restrict__ W_ab,
                 const float* __restrict__ b_ab,
                 const float* __restrict__ W_disc,
                 float* __restrict__ out)
{
    int b = blockIdx.x;
    int t = threadIdx.x;
    int v = t;                 // column ownership for t < 200
    int f = t % FD_;
    int quarter = t / FD_;
    int l = t & 31;            // lane
    int wj = t >> 5;           // warp id == step-within-chunk for epilogue

    __shared__ float2 ea_sm[CHUNK][VD_];       // 12.8 KB staged (erase,add)
    __shared__ float  w_sm[CHUNK][52];         // staged correlation weights
    __shared__ float  read_buf[CHUNK][VD_];    // banked read vectors
    __shared__ float  part_buf[CHUNK][VD_];    // banked summary partials
    __shared__ int    q_row[S_];
    __shared__ int    r_row[S_];

    const int base = b * S_;
    for (int i = t; i < S_; i += 256) {
        q_row[i] = q_data[base + i];
        r_row[i] = r_data[base + i];
    }

    float mv[M_];          // scalar memory state
    float Wreg[FD_];       // scalar W_sum column
    if (t < VD_) {
        #pragma unroll
        for (int m = 0; m < M_; m++) mv[m] = init_mem[m * VD_ + v];
        #pragma unroll
        for (int i = 0; i < FD_; i++)
            Wreg[i] = W_sum[(quarter * FD_ + i) * FD_ + f];
    }

    // per-lane epilogue constants (same for every warp)
    float wab1 = W_ab[l];
    float wd1  = W_disc[l];
    float wab2 = (l + 32 < FD_) ? W_ab[l + 32]   : 0.f;
    float wd2  = (l + 32 < FD_) ? W_disc[l + 32] : 0.f;
    float b_ab0 = b_ab[0];
    __syncthreads();   // q_row/r_row ready

    for (int c = 0; c < NCHUNK; c++) {
        const int s0 = c * CHUNK;

        // ---- stage this chunk's tables into smem ----
        if (t < VD_) {
            for (int j = 0; j < CHUNK; j++) {
                int qq = q_row[s0 + j], rr = r_row[s0 + j];
                ea_sm[j][t] = __ldg(reinterpret_cast<const float2*>(
                                  &g_ea_tab[((qq * 4 + rr) * VD_ + t) * 2]));
            }
        }
        for (int i = t; i < CHUNK * M_; i += 256) {
            int j = i / M_, m = i - j * M_;
            w_sm[j][m] = __ldg(&g_corr_tab[q_row[s0 + j] * M_ + m]);
        }
        __syncthreads();                               // BAR A: tables ready

        // ---- 8 barrier-free memory update steps (4-way rd chains) ----
        if (t < VD_) {
            for (int j = 0; j < CHUNK; j++) {
                float2 ea = ea_sm[j][v];
                float e = ea.x, a = ea.y;
                float rd0 = 0.f, rd1 = 0.f, rd2 = 0.f, rd3 = 0.f;
                #pragma unroll
                for (int m = 0; m < 48; m += 4) {
                    float2 wA = *reinterpret_cast<const float2*>(&w_sm[j][m]);
                    float2 wB = *reinterpret_cast<const float2*>(&w_sm[j][m + 2]);
                    float o0 = mv[m], o1 = mv[m + 1];
                    float o2 = mv[m + 2], o3 = mv[m + 3];
                    rd0 = fmaf(wA.x, o0, rd0);
                    rd1 = fmaf(wA.y, o1, rd1);
                    rd2 = fmaf(wB.x, o2, rd2);
                    rd3 = fmaf(wB.y, o3, rd3);
                    mv[m]     = fmaf(wA.x, fmaf(-o0, e, a), o0);
                    mv[m + 1] = fmaf(wA.y, fmaf(-o1, e, a), o1);
                    mv[m + 2] = fmaf(wB.x, fmaf(-o2, e, a), o2);
                    mv[m + 3] = fmaf(wB.y, fmaf(-o3, e, a), o3);
                }
                {   // tail m = 48, 49
                    float2 wA = *reinterpret_cast<const float2*>(&w_sm[j][48]);
                    float o0 = mv[48], o1 = mv[49];
                    rd0 = fmaf(wA.x, o0, rd0);
                    rd1 = fmaf(wA.y, o1, rd1);
                    mv[48] = fmaf(wA.x, fmaf(-o0, e, a), o0);
                    mv[49] = fmaf(wA.y, fmaf(-o1, e, a), o1);
                }
                read_buf[j][v] = (rd0 + rd1) + (rd2 + rd3);
            }
        }
        __syncthreads();                               // BAR B: reads ready

        // ---- epilogue-table prefetch: warp wj owns step s0+wj ----
        int qe_ = q_row[s0 + wj];
        float sq1 = __ldg(&g_sumq_tab[qe_ * FD_ + l]);
        float sq2 = (l + 32 < FD_) ? __ldg(&g_sumq_tab[qe_ * FD_ + l + 32]) : 0.f;
        float be0 = 0.f, be1 = 0.f, be2 = 0.f, dq = 0.f;
        if (l == 0) {
            be0 = g_beta_tab[qe_ * 4 + 0];
            be1 = g_beta_tab[qe_ * 4 + 1];
            be2 = g_beta_tab[qe_ * 4 + 2];
            dq  = g_dq_tab[qe_];
        }

        // ---- summary partials for all 8 steps (4-way acc chains) ----
        if (t < VD_) {
            const int qb = quarter * FD_;
            for (int j = 0; j < CHUNK; j++) {
                float a0 = 0.f, a1 = 0.f, a2 = 0.f, a3 = 0.f;
                #pragma unroll
                for (int i = 0; i < 48; i += 4) {
                    float2 rA = *reinterpret_cast<const float2*>(&read_buf[j][qb + i]);
                    float2 rB = *reinterpret_cast<const float2*>(&read_buf[j][qb + i + 2]);
                    a0 = fmaf(rA.x, Wreg[i],     a0);
                    a1 = fmaf(rA.y, Wreg[i + 1], a1);
                    a2 = fmaf(rB.x, Wreg[i + 2], a2);
                    a3 = fmaf(rB.y, Wreg[i + 3], a3);
                }
                {   // tail i = 48, 49
                    float2 rA = *reinterpret_cast<const float2*>(&read_buf[j][qb + 48]);
                    a0 = fmaf(rA.x, Wreg[48], a0);
                    a1 = fmaf(rA.y, Wreg[49], a1);
                }
                part_buf[j][t] = (a0 + a1) + (a2 + a3);
            }
        }
        __syncthreads();                               // BAR C: partials ready

        // ---- 8 concurrent epilogues, one per warp ----
        {
            float th_p, al_p;
            {
                float Sf = part_buf[wj][l] + part_buf[wj][l + 50] +
                           part_buf[wj][l + 100] + part_buf[wj][l + 150] + sq1;
                float sf = tanhf(Sf);
                th_p = sf * wab1;
                al_p = sf * wd1;
            }
            if (l + 32 < FD_) {
                int f2 = l + 32;
                float Sf = part_buf[wj][f2] + part_buf[wj][f2 + 50] +
                           part_buf[wj][f2 + 100] + part_buf[wj][f2 + 150] + sq2;
                float sf = tanhf(Sf);
                th_p = fmaf(sf, wab2, th_p);
                al_p = fmaf(sf, wd2, al_p);
            }
            #pragma unroll
            for (int o = 16; o > 0; o >>= 1) {
                th_p += __shfl_down_sync(0xffffffffu, th_p, o);
                al_p += __shfl_down_sync(0xffffffffu, al_p, o);
            }
            if (l == 0) {
                float theta = 3.0f * (th_p + b_ab0);
                float alpha = softplusf(al_p + dq);
                float d0 = theta - be0;
                float d1 = theta - be1;
                float d2 = theta - be2;
                float c0 = alpha * d0;
                float c1 = alpha * (d0 + d1);
                float c2 = alpha * (d0 + d1 + d2);
                float mx = fmaxf(0.0f, fmaxf(c0, fmaxf(c1, c2)));
                float e0 = expf(0.0f - mx);
                float e1 = expf(c0 - mx);
                float e2 = expf(c1 - mx);
                float e3 = expf(c2 - mx);
                float inv = 1.0f / (e0 + e1 + e2 + e3);
                float4 p = make_float4(e0 * inv, e1 * inv, e2 * inv, e3 * inv);
                reinterpret_cast<float4*>(out)[base + s0 + wj] = p;
            }
        }
        // Hazard audit: identical barrier structure to the 283us version —
        // ea_sm/w_sm writes (c+1) occur after BAR C(c) (readers done pre-BAR B);
        // read_buf writers (c+1) after BAR A(c+1) > partial readers (c);
        // part_buf writers (c+1) after BAR B(c+1) > epilogue readers (c).
    }
}

// ---------------- launch ---------------------------------------------
extern "C" void kernel_launch(void* const* d_in, const int* in_sizes, int n_in,
                              void* d_out, int out_size)
{
    const int*   q_data   = (const int*)  d_in[0];
    const int*   r_data   = (const int*)  d_in[1];
    const float* q_tab    = (const float*)d_in[2];
    const float* key_mem  = (const float*)d_in[3];
    const float* init_mem = (const float*)d_in[4];
    const float* W_qk     = (const float*)d_in[5];
    const float* b_qk     = (const float*)d_in[6];
    const float* W_v3     = (const float*)d_in[7];
    const float* b_v      = (const float*)d_in[8];
    const float* W_e      = (const float*)d_in[9];
    const float* b_e      = (const float*)d_in[10];
    const float* W_a      = (const float*)d_in[11];
    const float* b_a      = (const float*)d_in[12];
    const float* W_sum    = (const float*)d_in[13];
    const float* b_sum    = (const float*)d_in[14];
    const float* W_ab     = (const float*)d_in[15];
    const float* b_ab     = (const float*)d_in[16];
    const float* W_th     = (const float*)d_in[17];
    const float* b_th     = (const float*)d_in[18];
    const float* W_disc   = (const float*)d_in[19];
    const float* b_disc   = (const float*)d_in[20];
    float* out = (float*)d_out;

    qtab_kernel<<<NQT, 64>>>(q_tab, key_mem, W_qk, b_qk, W_sum, b_sum,
                             W_th, b_th, W_disc, b_disc);
    ea_kernel<<<(NROW + EA_ROWS - 1) / EA_ROWS, 256>>>(W_v3, b_v, W_e, b_e, W_a, b_a);
    scan_kernel<<<B_, 256>>>(q_data, r_data, init_mem, W_sum, W_ab, b_ab,
                             W_disc, out);
}

// round 11
// speedup vs baseline: 1.1618x; 1.0113x over previous
#include <cuda_runtime.h>
#include <math.h>

// Problem constants
#define B_   256
#define S_   200
#define NQ_  400
#define K_   4
#define M_   50
#define KD_  50
#define VD_  200
#define FD_  50
#define NQT  (NQ_ + 1)        // 401 q values
#define NROW (NQT * K_)       // 1604 (q,r) rows
#define CHUNK 8
#define NCHUNK (S_ / CHUNK)   // 25

typedef unsigned long long u64;

// ---------------- packed f32x2 helpers (Blackwell FFMA2) -------------
__device__ __forceinline__ u64 pack2(float lo, float hi) {
    u64 r; asm("mov.b64 %0, {%1,%2};" : "=l"(r) : "f"(lo), "f"(hi)); return r;
}
__device__ __forceinline__ u64 fma2(u64 a, u64 b, u64 c) {
    u64 r; asm("fma.rn.f32x2 %0, %1, %2, %3;" : "=l"(r) : "l"(a), "l"(b), "l"(c));
    return r;
}
__device__ __forceinline__ float hsum2(u64 p) {
    float a, b; asm("mov.b64 {%0,%1}, %2;" : "=f"(a), "=f"(b) : "l"(p));
    return a + b;
}

// ---------------- Precomputed tables (device scratch) ----------------
__device__ float g_corr_tab[NQT * M_];       // softmax(tanh(qemb@Wqk)@key^T)
__device__ float g_sumq_tab[NQT * FD_];      // qemb @ W_sum[200:250] + b_sum
__device__ float g_beta_tab[NQT * 4];        // tanh(qemb@W_th + b_th) (padded)
__device__ float g_dq_tab[NQT];              // qemb @ W_disc[50:100] + b_disc
__device__ float g_ea_tab[NROW * VD_ * 2];   // interleaved (erase, add) per (q,r) row

// ---------------- Kernel 1: q-indexed tables -------------------------
__global__ void qtab_kernel(const float* __restrict__ q_tab,
                            const float* __restrict__ key_mem,
                            const float* __restrict__ W_qk,
                            const float* __restrict__ b_qk,
                            const float* __restrict__ W_sum,
                            const float* __restrict__ b_sum,
                            const float* __restrict__ W_th,
                            const float* __restrict__ b_th,
                            const float* __restrict__ W_disc,
                            const float* __restrict__ b_disc)
{
    int q = blockIdx.x;
    int t = threadIdx.x;
    __shared__ float qe[KD_];
    __shared__ float qk[KD_];
    __shared__ float lg[M_];
    __shared__ float red[2];

    if (t < KD_) qe[t] = q_tab[q * KD_ + t];
    __syncthreads();

    if (t < KD_) {
        float acc = b_qk[t];
        #pragma unroll 10
        for (int d = 0; d < KD_; d++) acc = fmaf(qe[d], W_qk[d * KD_ + t], acc);
        qk[t] = tanhf(acc);
        float s = b_sum[t];
        #pragma unroll 10
        for (int d = 0; d < KD_; d++) s = fmaf(qe[d], W_sum[(VD_ + d) * FD_ + t], s);
        g_sumq_tab[q * FD_ + t] = s;
    }
    if (t < 3) {
        float acc = b_th[t];
        for (int d = 0; d < KD_; d++) acc = fmaf(qe[d], W_th[d * 3 + t], acc);
        g_beta_tab[q * 4 + t] = tanhf(acc);
    }
    if (t == 63) {
        float acc = b_disc[0];
        for (int d = 0; d < KD_; d++) acc = fmaf(qe[d], W_disc[KD_ + d], acc);
        g_dq_tab[q] = acc;
    }
    __syncthreads();

    if (t < M_) {
        float acc = 0.f;
        #pragma unroll 10
        for (int d = 0; d < KD_; d++) acc = fmaf(qk[d], key_mem[t * KD_ + d], acc);
        lg[t] = acc;
    }
    __syncthreads();
    if (t == 0) {
        float mx = -1e30f;
        for (int m = 0; m < M_; m++) mx = fmaxf(mx, lg[m]);
        red[0] = mx;
    }
    __syncthreads();
    if (t < M_) lg[t] = expf(lg[t] - red[0]);
    __syncthreads();
    if (t == 0) {
        float s = 0.f;
        for (int m = 0; m < M_; m++) s += lg[m];
        red[1] = 1.f / s;
    }
    __syncthreads();
    if (t < M_) g_corr_tab[q * M_ + t] = lg[t] * red[1];
}

// ---------------- Kernel 2: erase/add tables over 1604 rows ----------
#define EA_ROWS 16
__global__ void ea_kernel(const float* __restrict__ W_v3,
                          const float* __restrict__ b_v,
                          const float* __restrict__ W_e,
                          const float* __restrict__ b_e,
                          const float* __restrict__ W_a,
                          const float* __restrict__ b_a)
{
    __shared__ float ve[EA_ROWS][VD_];
    int t = threadIdx.x;
    int row0 = blockIdx.x * EA_ROWS;

    for (int i = t; i < EA_ROWS * VD_; i += blockDim.x) {
        int rr = i / VD_;
        int d  = i - rr * VD_;
        int row = row0 + rr;
        if (row < NROW) {
            int q = row >> 2;
            int r = row & 3;
            float val = b_v[d];
            if (q > 0) {
                int idx = q - 1;
                #pragma unroll
                for (int k = 0; k < K_; k++) {
                    int dd = (k > r) ? (k - r) : (r - k);
                    float wc = 1.0f - (float)dd / 3.0f;
                    if (wc > 0.0f)
                        val = fmaf(wc, W_v3[(k * NQ_ + idx) * VD_ + d], val);
                }
            }
            ve[rr][d] = val;
        }
    }
    __syncthreads();

    if (t < VD_) {
        int v = t;
        float acce[EA_ROWS], acca[EA_ROWS];
        #pragma unroll
        for (int rr = 0; rr < EA_ROWS; rr++) { acce[rr] = 0.f; acca[rr] = 0.f; }
        for (int d = 0; d < VD_; d++) {
            float we = W_e[d * VD_ + v];
            float wa = W_a[d * VD_ + v];
            #pragma unroll
            for (int rr = 0; rr < EA_ROWS; rr++) {
                float x = ve[rr][d];
                acce[rr] = fmaf(x, we, acce[rr]);
                acca[rr] = fmaf(x, wa, acca[rr]);
            }
        }
        float bev = b_e[v], bav = b_a[v];
        #pragma unroll
        for (int rr = 0; rr < EA_ROWS; rr++) {
            int row = row0 + rr;
            if (row < NROW) {
                float2 ea;
                ea.x = 1.0f / (1.0f + expf(-(acce[rr] + bev)));   // erase
                ea.y = tanhf(acca[rr] + bav);                     // add
                *reinterpret_cast<float2*>(&g_ea_tab[(row * VD_ + v) * 2]) = ea;
            }
        }
    }
}

// ---------------- Kernel 3: chunked scan, packed-f32x2 update --------
__device__ __forceinline__ float softplusf(float x) {
    return (x > 20.0f) ? x : log1pf(expf(x));
}

__global__ __launch_bounds__(256, 2)
void scan_kernel(const int* __restrict__ q_data,
                 const int* __restrict__ r_data,
                 const float* __restrict__ init_mem,
                 const float* __restrict__ W_sum,
                 const float* __restrict__ W_ab,
                 const float* __restrict__ b_ab,
                 const float* __restrict__ W_disc,
                 float* __restrict__ out)
{
    int b = blockIdx.x;
    int t = threadIdx.x;
    int v = t;                 // column ownership for t < 200
    int f = t % FD_;
    int quarter = t / FD_;
    int l = t & 31;            // lane
    int wj = t >> 5;           // warp id == step-within-chunk for epilogue

    __shared__ float2 ea_sm[CHUNK][VD_];       // 12.8 KB staged (erase,add)
    __shared__ float  w_sm[CHUNK][52];         // staged correlation weights
    __shared__ float  read_buf[CHUNK][VD_];    // banked read vectors
    __shared__ float  part_buf[CHUNK][VD_];    // banked summary partials
    __shared__ int    q_row[S_];
    __shared__ int    r_row[S_];

    const int base = b * S_;
    for (int i = t; i < S_; i += 256) {
        q_row[i] = q_data[base + i];
        r_row[i] = r_data[base + i];
    }

    u64   mv2[M_ / 2];     // packed memory state: (m, m+1) per slot
    float Wreg[FD_];       // scalar W_sum column (unconstrained regs)
    if (t < VD_) {
        #pragma unroll
        for (int m = 0; m < M_; m += 2)
            mv2[m >> 1] = pack2(init_mem[m * VD_ + v], init_mem[(m + 1) * VD_ + v]);
        #pragma unroll
        for (int i = 0; i < FD_; i++)
            Wreg[i] = W_sum[(quarter * FD_ + i) * FD_ + f];
    }

    // per-lane epilogue constants (same for every warp)
    float wab1 = W_ab[l];
    float wd1  = W_disc[l];
    float wab2 = (l + 32 < FD_) ? W_ab[l + 32]   : 0.f;
    float wd2  = (l + 32 < FD_) ? W_disc[l + 32] : 0.f;
    float b_ab0 = b_ab[0];
    __syncthreads();   // q_row/r_row ready

    for (int c = 0; c < NCHUNK; c++) {
        const int s0 = c * CHUNK;

        // ---- stage this chunk's tables into smem ----
        if (t < VD_) {
            for (int j = 0; j < CHUNK; j++) {
                int qq = q_row[s0 + j], rr = r_row[s0 + j];
                ea_sm[j][t] = __ldg(reinterpret_cast<const float2*>(
                                  &g_ea_tab[((qq * 4 + rr) * VD_ + t) * 2]));
            }
        }
        for (int i = t; i < CHUNK * M_; i += 256) {
            int j = i / M_, m = i - j * M_;
            w_sm[j][m] = __ldg(&g_corr_tab[q_row[s0 + j] * M_ + m]);
        }
        __syncthreads();                               // BAR A: tables ready

        // ---- 8 barrier-free memory update steps (packed f32x2) ----
        if (t < VD_) {
            for (int j = 0; j < CHUNK; j++) {
                float2 ea = ea_sm[j][v];
                u64 ne2 = pack2(-ea.x, -ea.x);    // (-e, -e)
                u64 a2  = pack2(ea.y, ea.y);      // ( a,  a)
                u64 rdA = 0, rdB = 0;             // +0.0f packed
                #pragma unroll
                for (int m = 0; m < 48; m += 4) {
                    u64 wA = *reinterpret_cast<const u64*>(&w_sm[j][m]);
                    u64 wB = *reinterpret_cast<const u64*>(&w_sm[j][m + 2]);
                    u64 oA = mv2[(m >> 1)];
                    u64 oB = mv2[(m >> 1) + 1];
                    rdA = fma2(wA, oA, rdA);
                    rdB = fma2(wB, oB, rdB);
                    mv2[(m >> 1)]     = fma2(wA, fma2(oA, ne2, a2), oA);
                    mv2[(m >> 1) + 1] = fma2(wB, fma2(oB, ne2, a2), oB);
                }
                {   // tail m = 48, 49
                    u64 wA = *reinterpret_cast<const u64*>(&w_sm[j][48]);
                    u64 oA = mv2[24];
                    rdA = fma2(wA, oA, rdA);
                    mv2[24] = fma2(wA, fma2(oA, ne2, a2), oA);
                }
                read_buf[j][v] = hsum2(rdA) + hsum2(rdB);
            }
        }
        __syncthreads();                               // BAR B: reads ready

        // ---- epilogue-table prefetch: warp wj owns step s0+wj ----
        int qe_ = q_row[s0 + wj];
        float sq1 = __ldg(&g_sumq_tab[qe_ * FD_ + l]);
        float sq2 = (l + 32 < FD_) ? __ldg(&g_sumq_tab[qe_ * FD_ + l + 32]) : 0.f;
        float be0 = 0.f, be1 = 0.f, be2 = 0.f, dq = 0.f;
        if (l == 0) {
            be0 = g_beta_tab[qe_ * 4 + 0];
            be1 = g_beta_tab[qe_ * 4 + 1];
            be2 = g_beta_tab[qe_ * 4 + 2];
            dq  = g_dq_tab[qe_];
        }

        // ---- summary partials for all 8 steps (scalar 4-way chains) ----
        if (t < VD_) {
            const int qb = quarter * FD_;
            for (int j = 0; j < CHUNK; j++) {
                float a0 = 0.f, a1 = 0.f, a2 = 0.f, a3 = 0.f;
                #pragma unroll
                for (int i = 0; i < 48; i += 4) {
                    float2 rA = *reinterpret_cast<const float2*>(&read_buf[j][qb + i]);
                    float2 rB = *reinterpret_cast<const float2*>(&read_buf[j][qb + i + 2]);
                    a0 = fmaf(rA.x, Wreg[i],     a0);
                    a1 = fmaf(rA.y, Wreg[i + 1], a1);
                    a2 = fmaf(rB.x, Wreg[i + 2], a2);
                    a3 = fmaf(rB.y, Wreg[i + 3], a3);
                }
                {   // tail i = 48, 49
                    float2 rA = *reinterpret_cast<const float2*>(&read_buf[j][qb + 48]);
                    a0 = fmaf(rA.x, Wreg[48], a0);
                    a1 = fmaf(rA.y, Wreg[49], a1);
                }
                part_buf[j][t] = (a0 + a1) + (a2 + a3);
            }
        }
        __syncthreads();                               // BAR C: partials ready

        // ---- 8 concurrent epilogues, one per warp ----
        {
            float th_p, al_p;
            {
                float Sf = part_buf[wj][l] + part_buf[wj][l + 50] +
                           part_buf[wj][l + 100] + part_buf[wj][l + 150] + sq1;
                float sf = tanhf(Sf);
                th_p = sf * wab1;
                al_p = sf * wd1;
            }
            if (l + 32 < FD_) {
                int f2 = l + 32;
                float Sf = part_buf[wj][f2] + part_buf[wj][f2 + 50] +
                           part_buf[wj][f2 + 100] + part_buf[wj][f2 + 150] + sq2;
                float sf = tanhf(Sf);
                th_p = fmaf(sf, wab2, th_p);
                al_p = fmaf(sf, wd2, al_p);
            }
            #pragma unroll
            for (int o = 16; o > 0; o >>= 1) {
                th_p += __shfl_down_sync(0xffffffffu, th_p, o);
                al_p += __shfl_down_sync(0xffffffffu, al_p, o);
            }
            if (l == 0) {
                float theta = 3.0f * (th_p + b_ab0);
                float alpha = softplusf(al_p + dq);
                float d0 = theta - be0;
                float d1 = theta - be1;
                float d2 = theta - be2;
                float c0 = alpha * d0;
                float c1 = alpha * (d0 + d1);
                float c2 = alpha * (d0 + d1 + d2);
                float mx = fmaxf(0.0f, fmaxf(c0, fmaxf(c1, c2)));
                float e0 = expf(0.0f - mx);
                float e1 = expf(c0 - mx);
                float e2 = expf(c1 - mx);
                float e3 = expf(c2 - mx);
                float inv = 1.0f / (e0 + e1 + e2 + e3);
                float4 p = make_float4(e0 * inv, e1 * inv, e2 * inv, e3 * inv);
                reinterpret_cast<float4*>(out)[base + s0 + wj] = p;
            }
        }
        // Hazard audit: identical barrier structure to the R7/R9 versions —
        // ea_sm/w_sm writes (c+1) occur after BAR C(c) (readers done pre-BAR B);
        // read_buf writers (c+1) after BAR A(c+1) > partial readers (c);
        // part_buf writers (c+1) after BAR B(c+1) > epilogue readers (c).
    }
}

// ---------------- launch ---------------------------------------------
extern "C" void kernel_launch(void* const* d_in, const int* in_sizes, int n_in,
                              void* d_out, int out_size)
{
    const int*   q_data   = (const int*)  d_in[0];
    const int*   r_data   = (const int*)  d_in[1];
    const float* q_tab    = (const float*)d_in[2];
    const float* key_mem  = (const float*)d_in[3];
    const float* init_mem = (const float*)d_in[4];
    const float* W_qk     = (const float*)d_in[5];
    const float* b_qk     = (const float*)d_in[6];
    const float* W_v3     = (const float*)d_in[7];
    const float* b_v      = (const float*)d_in[8];
    const float* W_e      = (const float*)d_in[9];
    const float* b_e      = (const float*)d_in[10];
    const float* W_a      = (const float*)d_in[11];
    const float* b_a      = (const float*)d_in[12];
    const float* W_sum    = (const float*)d_in[13];
    const float* b_sum    = (const float*)d_in[14];
    const float* W_ab     = (const float*)d_in[15];
    const float* b_ab     = (const float*)d_in[16];
    const float* W_th     = (const float*)d_in[17];
    const float* b_th     = (const float*)d_in[18];
    const float* W_disc   = (const float*)d_in[19];
    const float* b_disc   = (const float*)d_in[20];
    float* out = (float*)d_out;

    qtab_kernel<<<NQT, 64>>>(q_tab, key_mem, W_qk, b_qk, W_sum, b_sum,
                             W_th, b_th, W_disc, b_disc);
    ea_kernel<<<(NROW + EA_ROWS - 1) / EA_ROWS, 256>>>(W_v3, b_v, W_e, b_e, W_a, b_a);
    scan_kernel<<<B_, 256>>>(q_data, r_data, init_mem, W_sum, W_ab, b_ab,
                             W_disc, out);
}

// round 14
// speedup vs baseline: 1.2708x; 1.0938x over previous
#include <cuda_runtime.h>
#include <math.h>

// Problem constants
#define B_   256
#define S_   200
#define NQ_  400
#define K_   4
#define M_   50
#define KD_  50
#define VD_  200
#define FD_  50
#define NQT  (NQ_ + 1)        // 401 q values
#define NROW (NQT * K_)       // 1604 (q,r) rows
#define CHUNK 10
#define NCHUNK (S_ / CHUNK)   // 20

typedef unsigned long long u64;

// ---------------- packed f32x2 helpers (Blackwell FFMA2) -------------
__device__ __forceinline__ u64 pack2(float lo, float hi) {
    u64 r; asm("mov.b64 %0, {%1,%2};" : "=l"(r) : "f"(lo), "f"(hi)); return r;
}
__device__ __forceinline__ u64 fma2(u64 a, u64 b, u64 c) {
    u64 r; asm("fma.rn.f32x2 %0, %1, %2, %3;" : "=l"(r) : "l"(a), "l"(b), "l"(c));
    return r;
}
__device__ __forceinline__ float hsum2(u64 p) {
    float a, b; asm("mov.b64 {%0,%1}, %2;" : "=f"(a), "=f"(b) : "l"(p));
    return a + b;
}

// ---------------- Precomputed tables (device scratch) ----------------
__device__ float g_corr_tab[NQT * M_];       // softmax(tanh(qemb@Wqk)@key^T)
__device__ float g_sumq_tab[NQT * FD_];      // qemb @ W_sum[200:250] + b_sum
__device__ float g_beta_tab[NQT * 4];        // tanh(qemb@W_th + b_th) (padded)
__device__ float g_dq_tab[NQT];              // qemb @ W_disc[50:100] + b_disc
__device__ float g_ea_tab[NROW * VD_ * 2];   // interleaved (erase, add) per (q,r) row

// ---------------- Kernel 1: q-indexed tables -------------------------
__global__ void qtab_kernel(const float* __restrict__ q_tab,
                            const float* __restrict__ key_mem,
                            const float* __restrict__ W_qk,
                            const float* __restrict__ b_qk,
                            const float* __restrict__ W_sum,
                            const float* __restrict__ b_sum,
                            const float* __restrict__ W_th,
                            const float* __restrict__ b_th,
                            const float* __restrict__ W_disc,
                            const float* __restrict__ b_disc)
{
    int q = blockIdx.x;
    int t = threadIdx.x;
    __shared__ float qe[KD_];
    __shared__ float qk[KD_];
    __shared__ float lg[M_];
    __shared__ float red[2];

    if (t < KD_) qe[t] = q_tab[q * KD_ + t];
    __syncthreads();

    if (t < KD_) {
        float acc = b_qk[t];
        #pragma unroll 10
        for (int d = 0; d < KD_; d++) acc = fmaf(qe[d], W_qk[d * KD_ + t], acc);
        qk[t] = tanhf(acc);
        float s = b_sum[t];
        #pragma unroll 10
        for (int d = 0; d < KD_; d++) s = fmaf(qe[d], W_sum[(VD_ + d) * FD_ + t], s);
        g_sumq_tab[q * FD_ + t] = s;
    }
    if (t < 3) {
        float acc = b_th[t];
        for (int d = 0; d < KD_; d++) acc = fmaf(qe[d], W_th[d * 3 + t], acc);
        g_beta_tab[q * 4 + t] = tanhf(acc);
    }
    if (t == 63) {
        float acc = b_disc[0];
        for (int d = 0; d < KD_; d++) acc = fmaf(qe[d], W_disc[KD_ + d], acc);
        g_dq_tab[q] = acc;
    }
    __syncthreads();

    if (t < M_) {
        float acc = 0.f;
        #pragma unroll 10
        for (int d = 0; d < KD_; d++) acc = fmaf(qk[d], key_mem[t * KD_ + d], acc);
        lg[t] = acc;
    }
    __syncthreads();
    if (t == 0) {
        float mx = -1e30f;
        for (int m = 0; m < M_; m++) mx = fmaxf(mx, lg[m]);
        red[0] = mx;
    }
    __syncthreads();
    if (t < M_) lg[t] = expf(lg[t] - red[0]);
    __syncthreads();
    if (t == 0) {
        float s = 0.f;
        for (int m = 0; m < M_; m++) s += lg[m];
        red[1] = 1.f / s;
    }
    __syncthreads();
    if (t < M_) g_corr_tab[q * M_ + t] = lg[t] * red[1];
}

// ---------------- Kernel 2: erase/add tables over 1604 rows ----------
#define EA_ROWS 8
__global__ void ea_kernel(const float* __restrict__ W_v3,
                          const float* __restrict__ b_v,
                          const float* __restrict__ W_e,
                          const float* __restrict__ b_e,
                          const float* __restrict__ W_a,
                          const float* __restrict__ b_a)
{
    __shared__ float ve[EA_ROWS][VD_];
    int t = threadIdx.x;
    int row0 = blockIdx.x * EA_ROWS;

    for (int i = t; i < EA_ROWS * VD_; i += blockDim.x) {
        int rr = i / VD_;
        int d  = i - rr * VD_;
        int row = row0 + rr;
        if (row < NROW) {
            int q = row >> 2;
            int r = row & 3;
            float val = b_v[d];
            if (q > 0) {
                int idx = q - 1;
                #pragma unroll
                for (int k = 0; k < K_; k++) {
                    int dd = (k > r) ? (k - r) : (r - k);
                    float wc = 1.0f - (float)dd / 3.0f;
                    if (wc > 0.0f)
                        val = fmaf(wc, W_v3[(k * NQ_ + idx) * VD_ + d], val);
                }
            }
            ve[rr][d] = val;
        }
    }
    __syncthreads();

    if (t < VD_) {
        int v = t;
        float acce[EA_ROWS], acca[EA_ROWS];
        #pragma unroll
        for (int rr = 0; rr < EA_ROWS; rr++) { acce[rr] = 0.f; acca[rr] = 0.f; }
        #pragma unroll 4
        for (int d = 0; d < VD_; d++) {
            float we = W_e[d * VD_ + v];
            float wa = W_a[d * VD_ + v];
            #pragma unroll
            for (int rr = 0; rr < EA_ROWS; rr++) {
                float x = ve[rr][d];
                acce[rr] = fmaf(x, we, acce[rr]);
                acca[rr] = fmaf(x, wa, acca[rr]);
            }
        }
        float bev = b_e[v], bav = b_a[v];
        #pragma unroll
        for (int rr = 0; rr < EA_ROWS; rr++) {
            int row = row0 + rr;
            if (row < NROW) {
                float2 ea;
                ea.x = 1.0f / (1.0f + expf(-(acce[rr] + bev)));   // erase
                ea.y = tanhf(acca[rr] + bav);                     // add
                *reinterpret_cast<float2*>(&g_ea_tab[(row * VD_ + v) * 2]) = ea;
            }
        }
    }
}

// ---------------- Kernel 3: chunked scan (CHUNK=10) ------------------
__device__ __forceinline__ float softplusf(float x) {
    return (x > 20.0f) ? x : log1pf(expf(x));
}

__global__ __launch_bounds__(256, 2)
void scan_kernel(const int* __restrict__ q_data,
                 const int* __restrict__ r_data,
                 const float* __restrict__ init_mem,
                 const float* __restrict__ W_sum,
                 const float* __restrict__ W_ab,
                 const float* __restrict__ b_ab,
                 const float* __restrict__ W_disc,
                 float* __restrict__ out)
{
    int b = blockIdx.x;
    int t = threadIdx.x;
    int v = t;                 // column ownership for t < 200
    int f = t % FD_;
    int quarter = t / FD_;
    int l = t & 31;            // lane
    int wj = t >> 5;           // warp id (epilogue step owner)

    __shared__ __align__(16) float2 ea_sm[CHUNK][VD_];    // 16 KB
    __shared__ __align__(16) float  w_sm[CHUNK][52];      // 2.1 KB (rows 208B)
    __shared__ __align__(16) float  read_buf[CHUNK][208]; // 8.3 KB (4 blocks of 52)
    __shared__ float  part_buf[CHUNK][VD_];               // 8 KB
    __shared__ int    q_row[S_];
    __shared__ int    r_row[S_];

    const int base = b * S_;
    for (int i = t; i < S_; i += 256) {
        q_row[i] = q_data[base + i];
        r_row[i] = r_data[base + i];
    }

    u64   mv2[M_ / 2];     // packed memory state: (m, m+1) per slot
    float Wreg[FD_];       // scalar W_sum column (unconstrained regs)
    const int vslot = (t < VD_) ? ((t / FD_) * 52 + (t % FD_)) : 0; // padded slot
    if (t < VD_) {
        #pragma unroll
        for (int m = 0; m < M_; m += 2)
            mv2[m >> 1] = pack2(init_mem[m * VD_ + v], init_mem[(m + 1) * VD_ + v]);
        #pragma unroll
        for (int i = 0; i < FD_; i++)
            Wreg[i] = W_sum[(quarter * FD_ + i) * FD_ + f];
    }

    // per-lane epilogue constants (same for every warp)
    float wab1 = W_ab[l];
    float wd1  = W_disc[l];
    float wab2 = (l + 32 < FD_) ? W_ab[l + 32]   : 0.f;
    float wd2  = (l + 32 < FD_) ? W_disc[l + 32] : 0.f;
    float b_ab0 = b_ab[0];
    __syncthreads();   // q_row/r_row ready

    for (int c = 0; c < NCHUNK; c++) {
        const int s0 = c * CHUNK;

        // ---- stage this chunk's tables into smem ----
        if (t < VD_) {
            for (int j = 0; j < CHUNK; j++) {
                int qq = q_row[s0 + j], rr = r_row[s0 + j];
                ea_sm[j][t] = __ldg(reinterpret_cast<const float2*>(
                                  &g_ea_tab[((qq * 4 + rr) * VD_ + t) * 2]));
            }
        }
        for (int i = t; i < CHUNK * M_; i += 256) {
            int j = i / M_, m = i - j * M_;
            w_sm[j][m] = __ldg(&g_corr_tab[q_row[s0 + j] * M_ + m]);
        }
        __syncthreads();                               // BAR A: tables ready

        // ---- CHUNK barrier-free memory update steps (f32x2, LDS.64) ----
        if (t < VD_) {
            for (int j = 0; j < CHUNK; j++) {
                float2 ea = ea_sm[j][v];
                u64 ne2 = pack2(-ea.x, -ea.x);    // (-e, -e)
                u64 a2  = pack2(ea.y, ea.y);      // ( a,  a)
                u64 rdA = 0, rdB = 0;
                #pragma unroll
                for (int m = 0; m < 48; m += 4) {
                    u64 wA = *reinterpret_cast<const u64*>(&w_sm[j][m]);
                    u64 wB = *reinterpret_cast<const u64*>(&w_sm[j][m + 2]);
                    u64 oA = mv2[(m >> 1)];
                    u64 oB = mv2[(m >> 1) + 1];
                    rdA = fma2(wA, oA, rdA);
                    rdB = fma2(wB, oB, rdB);
                    mv2[(m >> 1)]     = fma2(wA, fma2(oA, ne2, a2), oA);
                    mv2[(m >> 1) + 1] = fma2(wB, fma2(oB, ne2, a2), oB);
                }
                {   // tail m = 48, 49
                    u64 wA = *reinterpret_cast<const u64*>(&w_sm[j][48]);
                    u64 oA = mv2[24];
                    rdA = fma2(wA, oA, rdA);
                    mv2[24] = fma2(wA, fma2(oA, ne2, a2), oA);
                }
                read_buf[j][vslot] = hsum2(rdA) + hsum2(rdB);
            }
        }
        __syncthreads();                               // BAR B: reads ready

        // ---- summary partials for all CHUNK steps (float4 broadcasts) ----
        if (t < VD_) {
            const int qb = quarter * 52;
            for (int j = 0; j < CHUNK; j++) {
                float a0 = 0.f, a1 = 0.f, a2 = 0.f, a3 = 0.f;
                #pragma unroll
                for (int i = 0; i < 48; i += 4) {
                    float4 r4 = *reinterpret_cast<const float4*>(&read_buf[j][qb + i]);
                    a0 = fmaf(r4.x, Wreg[i],     a0);
                    a1 = fmaf(r4.y, Wreg[i + 1], a1);
                    a2 = fmaf(r4.z, Wreg[i + 2], a2);
                    a3 = fmaf(r4.w, Wreg[i + 3], a3);
                }
                {   // tail i = 48, 49
                    float2 r2 = *reinterpret_cast<const float2*>(&read_buf[j][qb + 48]);
                    a0 = fmaf(r2.x, Wreg[48], a0);
                    a1 = fmaf(r2.y, Wreg[49], a1);
                }
                part_buf[j][t] = (a0 + a1) + (a2 + a3);
            }
        }
        __syncthreads();                               // BAR C: partials ready

        // ---- epilogues: warp wj handles steps wj, wj+8 (10 steps, 8 warps) ----
        for (int jj = wj; jj < CHUNK; jj += 8) {
            int qe_ = q_row[s0 + jj];
            float sq1 = __ldg(&g_sumq_tab[qe_ * FD_ + l]);
            float sq2 = (l + 32 < FD_) ? __ldg(&g_sumq_tab[qe_ * FD_ + l + 32]) : 0.f;
            float be0 = 0.f, be1 = 0.f, be2 = 0.f, dq = 0.f;
            if (l == 0) {
                be0 = g_beta_tab[qe_ * 4 + 0];
                be1 = g_beta_tab[qe_ * 4 + 1];
                be2 = g_beta_tab[qe_ * 4 + 2];
                dq  = g_dq_tab[qe_];
            }
            float th_p, al_p;
            {
                float Sf = part_buf[jj][l] + part_buf[jj][l + 50] +
                           part_buf[jj][l + 100] + part_buf[jj][l + 150] + sq1;
                float sf = tanhf(Sf);
                th_p = sf * wab1;
                al_p = sf * wd1;
            }
            if (l + 32 < FD_) {
                int f2 = l + 32;
                float Sf = part_buf[jj][f2] + part_buf[jj][f2 + 50] +
                           part_buf[jj][f2 + 100] + part_buf[jj][f2 + 150] + sq2;
                float sf = tanhf(Sf);
                th_p = fmaf(sf, wab2, th_p);
                al_p = fmaf(sf, wd2, al_p);
            }
            #pragma unroll
            for (int o = 16; o > 0; o >>= 1) {
                th_p += __shfl_down_sync(0xffffffffu, th_p, o);
                al_p += __shfl_down_sync(0xffffffffu, al_p, o);
            }
            if (l == 0) {
                float theta = 3.0f * (th_p + b_ab0);
                float alpha = softplusf(al_p + dq);
                float d0 = theta - be0;
                float d1 = theta - be1;
                float d2 = theta - be2;
                float c0 = alpha * d0;
                float c1 = alpha * (d0 + d1);
                float c2 = alpha * (d0 + d1 + d2);
                float mx = fmaxf(0.0f, fmaxf(c0, fmaxf(c1, c2)));
                float e0 = expf(0.0f - mx);
                float e1 = expf(c0 - mx);
                float e2 = expf(c1 - mx);
                float e3 = expf(c2 - mx);
                float inv = 1.0f / (e0 + e1 + e2 + e3);
                float4 p = make_float4(e0 * inv, e1 * inv, e2 * inv, e3 * inv);
                reinterpret_cast<float4*>(out)[base + s0 + jj] = p;
            }
        }
        // Hazard audit (same 3-barrier structure as R7/R9/R11):
        //  ea_sm/w_sm writes (c+1) occur after BAR C(c); readers done pre-BAR B(c).
        //  read_buf writers (c+1) after BAR A(c+1) > summary readers (c).
        //  part_buf writers (c+1) after BAR B(c+1) > epilogue readers (c).
    }
}

// ---------------- launch ---------------------------------------------
extern "C" void kernel_launch(void* const* d_in, const int* in_sizes, int n_in,
                              void* d_out, int out_size)
{
    const int*   q_data   = (const int*)  d_in[0];
    const int*   r_data   = (const int*)  d_in[1];
    const float* q_tab    = (const float*)d_in[2];
    const float* key_mem  = (const float*)d_in[3];
    const float* init_mem = (const float*)d_in[4];
    const float* W_qk     = (const float*)d_in[5];
    const float* b_qk     = (const float*)d_in[6];
    const float* W_v3     = (const float*)d_in[7];
    const float* b_v      = (const float*)d_in[8];
    const float* W_e      = (const float*)d_in[9];
    const float* b_e      = (const float*)d_in[10];
    const float* W_a      = (const float*)d_in[11];
    const float* b_a      = (const float*)d_in[12];
    const float* W_sum    = (const float*)d_in[13];
    const float* b_sum    = (const float*)d_in[14];
    const float* W_ab     = (const float*)d_in[15];
    const float* b_ab     = (const float*)d_in[16];
    const float* W_th     = (const float*)d_in[17];
    const float* b_th     = (const float*)d_in[18];
    const float* W_disc   = (const float*)d_in[19];
    const float* b_disc   = (const float*)d_in[20];
    float* out = (float*)d_out;

    qtab_kernel<<<NQT, 64>>>(q_tab, key_mem, W_qk, b_qk, W_sum, b_sum,
                             W_th, b_th, W_disc, b_disc);
    ea_kernel<<<(NROW + EA_ROWS - 1) / EA_ROWS, 256>>>(W_v3, b_v, W_e, b_e, W_a, b_a);
    scan_kernel<<<B_, 256>>>(q_data, r_data, init_mem, W_sum, W_ab, b_ab,
                             W_disc, out);
}